// round 1
// baseline (speedup 1.0000x reference)
#include <cuda_runtime.h>
#include <math.h>

// Problem constants
#define B_  32
#define C_  273
#define T_  3000
#define O_  270
#define D_  2048   // 2 * 32^2
#define NF  32

// Scratch (allocation-free rule: __device__ globals)
__device__ float g_emb[(size_t)B_ * C_ * D_];      // [B*C, 2048]
__device__ float g_scores[(size_t)B_ * O_ * C_];   // [B, 270, 273] -> softmaxed in place

// ---------------------------------------------------------------------------
// Kernel 1: fourier embedding.  emb[bc, i*32+j] = sin(2pi(px*i+py*j)),
//           emb[bc, 1024 + i*32+j] = cos(...)
// Range-reduce (mod 1) before sincos so accuracy holds even under fast-math.
// ---------------------------------------------------------------------------
__global__ __launch_bounds__(256) void emb_kernel(const float* __restrict__ layout) {
    int bc = blockIdx.x;
    float px = (layout[bc * 2 + 0] + 0.1f) / 1.2f;
    float py = (layout[bc * 2 + 1] + 0.1f) / 1.2f;
    float* e = g_emb + (size_t)bc * D_;
    for (int idx = threadIdx.x; idx < 1024; idx += blockDim.x) {
        int i = idx >> 5, j = idx & 31;
        float t = px * (float)i + py * (float)j;
        t -= floorf(t);
        float s, c;
        sincosf(6.28318530717958647692f * t, &s, &c);
        e[idx]        = s;
        e[idx + 1024] = c;
    }
}

// ---------------------------------------------------------------------------
// Kernel 2: scores[b,o,c] = sum_d heads[o,d] * emb[b,c,d]
// NT GEMM per batch: M=270 (o), N=273 (c), K=2048. Tiles 64x64x16, 4x4/thread.
// ---------------------------------------------------------------------------
__global__ __launch_bounds__(256) void scores_kernel(const float* __restrict__ heads) {
    __shared__ float As[16][64];
    __shared__ float Bs[16][64];
    int b  = blockIdx.z;
    int m0 = blockIdx.y * 64;   // o
    int n0 = blockIdx.x * 64;   // c
    const float* Bm = g_emb + (size_t)b * C_ * D_;
    int tid = threadIdx.x;
    int tr  = tid >> 2;            // 0..63 row within tile
    int tk4 = (tid & 3) << 2;      // 0,4,8,12
    int tm0 = (tid >> 4) << 2;
    int tn0 = (tid & 15) << 2;
    float acc[4][4] = {};

    for (int k0 = 0; k0 < D_; k0 += 16) {
        float4 av = make_float4(0.f, 0.f, 0.f, 0.f);
        float4 bv = make_float4(0.f, 0.f, 0.f, 0.f);
        if (m0 + tr < O_) av = *(const float4*)(heads + (size_t)(m0 + tr) * D_ + k0 + tk4);
        if (n0 + tr < C_) bv = *(const float4*)(Bm    + (size_t)(n0 + tr) * D_ + k0 + tk4);
        __syncthreads();
        As[tk4 + 0][tr] = av.x; As[tk4 + 1][tr] = av.y;
        As[tk4 + 2][tr] = av.z; As[tk4 + 3][tr] = av.w;
        Bs[tk4 + 0][tr] = bv.x; Bs[tk4 + 1][tr] = bv.y;
        Bs[tk4 + 2][tr] = bv.z; Bs[tk4 + 3][tr] = bv.w;
        __syncthreads();
#pragma unroll
        for (int k = 0; k < 16; k++) {
            float a[4], bb[4];
#pragma unroll
            for (int q = 0; q < 4; q++) { a[q] = As[k][tm0 + q]; bb[q] = Bs[k][tn0 + q]; }
#pragma unroll
            for (int i = 0; i < 4; i++)
#pragma unroll
                for (int j = 0; j < 4; j++) acc[i][j] = fmaf(a[i], bb[j], acc[i][j]);
        }
    }

    float* S = g_scores + (size_t)b * O_ * C_;
#pragma unroll
    for (int i = 0; i < 4; i++) {
        int m = m0 + tm0 + i;
        if (m >= O_) continue;
#pragma unroll
        for (int j = 0; j < 4; j++) {
            int n = n0 + tn0 + j;
            if (n < C_) S[m * C_ + n] = acc[i][j];
        }
    }
}

// ---------------------------------------------------------------------------
// Kernel 3: softmax over last dim (C_=273) of g_scores, in place.
// One warp per (b,o) row; 8640 rows.
// ---------------------------------------------------------------------------
__global__ __launch_bounds__(256) void softmax_kernel() {
    int warp = (blockIdx.x * blockDim.x + threadIdx.x) >> 5;
    int lane = threadIdx.x & 31;
    if (warp >= B_ * O_) return;
    float* row = g_scores + (size_t)warp * C_;

    float v[9];
    float m = -INFINITY;
#pragma unroll
    for (int i = 0; i < 9; i++) {
        int c = lane + i * 32;
        v[i] = (c < C_) ? row[c] : -INFINITY;
        m = fmaxf(m, v[i]);
    }
#pragma unroll
    for (int o = 16; o; o >>= 1) m = fmaxf(m, __shfl_xor_sync(0xffffffffu, m, o));
    float s = 0.f;
#pragma unroll
    for (int i = 0; i < 9; i++) {
        int c = lane + i * 32;
        if (c < C_) { v[i] = expf(v[i] - m); s += v[i]; }
    }
#pragma unroll
    for (int o = 16; o; o >>= 1) s += __shfl_xor_sync(0xffffffffu, s, o);
    float inv = 1.f / s;
#pragma unroll
    for (int i = 0; i < 9; i++) {
        int c = lane + i * 32;
        if (c < C_) row[c] = v[i] * inv;
    }
}

// ---------------------------------------------------------------------------
// Kernel 4: out[b,o,t] = sum_c W[b,o,c] * brain[b,c,t]
// NN GEMM per batch: M=270 (o), N=3000 (t), K=273 (c). Tiles 64x64x16.
// ---------------------------------------------------------------------------
__global__ __launch_bounds__(256) void out_kernel(const float* __restrict__ brain,
                                                  float* __restrict__ out) {
    __shared__ float As[16][64];
    __shared__ float Bs[16][64];
    int b  = blockIdx.z;
    int m0 = blockIdx.y * 64;   // o
    int n0 = blockIdx.x * 64;   // t
    const float* Wb = g_scores + (size_t)b * O_ * C_;
    const float* Xb = brain    + (size_t)b * C_ * T_;
    int tid = threadIdx.x;
    int ar  = tid >> 2;            // m row for A load
    int ak4 = (tid & 3) << 2;      // k offset for A load
    int bk  = tid >> 4;            // k row for B load
    int bn4 = (tid & 15) << 2;     // n offset for B load
    int tm0 = (tid >> 4) << 2;
    int tn0 = (tid & 15) << 2;
    float acc[4][4] = {};

    for (int k0 = 0; k0 < C_; k0 += 16) {
        float a[4];
#pragma unroll
        for (int q = 0; q < 4; q++) {
            int k = k0 + ak4 + q;
            a[q] = (m0 + ar < O_ && k < C_) ? Wb[(m0 + ar) * C_ + k] : 0.f;
        }
        float4 bv = make_float4(0.f, 0.f, 0.f, 0.f);
        int krow = k0 + bk;
        if (krow < C_) {
            const float* p = Xb + (size_t)krow * T_;
            if (n0 + bn4 + 3 < T_) {
                bv = *(const float4*)(p + n0 + bn4);
            } else {
                if (n0 + bn4 + 0 < T_) bv.x = p[n0 + bn4 + 0];
                if (n0 + bn4 + 1 < T_) bv.y = p[n0 + bn4 + 1];
                if (n0 + bn4 + 2 < T_) bv.z = p[n0 + bn4 + 2];
                if (n0 + bn4 + 3 < T_) bv.w = p[n0 + bn4 + 3];
            }
        }
        __syncthreads();
        As[ak4 + 0][ar] = a[0]; As[ak4 + 1][ar] = a[1];
        As[ak4 + 2][ar] = a[2]; As[ak4 + 3][ar] = a[3];
        *(float4*)&Bs[bk][bn4] = bv;
        __syncthreads();
#pragma unroll
        for (int k = 0; k < 16; k++) {
            float aa[4], bb[4];
#pragma unroll
            for (int q = 0; q < 4; q++) { aa[q] = As[k][tm0 + q]; bb[q] = Bs[k][tn0 + q]; }
#pragma unroll
            for (int i = 0; i < 4; i++)
#pragma unroll
                for (int j = 0; j < 4; j++) acc[i][j] = fmaf(aa[i], bb[j], acc[i][j]);
        }
    }

    float* Ob = out + (size_t)b * O_ * T_;
#pragma unroll
    for (int i = 0; i < 4; i++) {
        int m = m0 + tm0 + i;
        if (m >= O_) continue;
#pragma unroll
        for (int j = 0; j < 4; j++) {
            int n = n0 + tn0 + j;
            if (n < T_) Ob[(size_t)m * T_ + n] = acc[i][j];
        }
    }
}

// ---------------------------------------------------------------------------
extern "C" void kernel_launch(void* const* d_in, const int* in_sizes, int n_in,
                              void* d_out, int out_size) {
    const float* brain  = (const float*)d_in[0];  // [32, 273, 3000]
    const float* layout = (const float*)d_in[1];  // [32, 273, 2]
    const float* heads  = (const float*)d_in[2];  // [270, 2048]
    float* out = (float*)d_out;                   // [32, 270, 3000]

    emb_kernel<<<B_ * C_, 256>>>(layout);
    scores_kernel<<<dim3((C_ + 63) / 64, (O_ + 63) / 64, B_), 256>>>(heads);
    softmax_kernel<<<(B_ * O_ * 32 + 255) / 256, 256>>>();
    out_kernel<<<dim3((T_ + 63) / 64, (O_ + 63) / 64, B_), 256>>>(brain, out);
}